// round 1
// baseline (speedup 1.0000x reference)
#include <cuda_runtime.h>

#define N_NODE 100000
#define EMB    112
#define NNZ    1000000
#define BATCH  512
#define SEQL   50

// ---------------- scratch (device globals; no allocations allowed) ----------
__device__ int   g_cnt[N_NODE + 1];
__device__ int   g_row_ptr[N_NODE + 1];
__device__ int   g_row_fill[N_NODE];
__device__ float g_csr_val[NNZ];
__device__ int   g_csr_col[NNZ];
__device__ float g_buf1[(size_t)N_NODE * EMB];
__device__ float g_buf2[(size_t)N_NODE * EMB];
__device__ float g_sess[BATCH * EMB];
__device__ float g_tmp[BATCH * EMB];
__device__ float g_accum[BATCH * EMB];
__device__ float g_DA[BATCH * BATCH];

// ---------------- CSR build --------------------------------------------------
__global__ void k_zero_cnt() {
    int i = blockIdx.x * blockDim.x + threadIdx.x;
    if (i <= N_NODE) g_cnt[i] = 0;
}

__global__ void k_count(const int* __restrict__ rows) {
    int i = blockIdx.x * blockDim.x + threadIdx.x;
    if (i < NNZ) atomicAdd(&g_cnt[rows[i]], 1);
}

// single-block exclusive scan over N_NODE counts (tiled Hillis-Steele)
__global__ void k_scan() {
    __shared__ int sdata[1024];
    __shared__ int s_running;
    if (threadIdx.x == 0) s_running = 0;
    __syncthreads();
    for (int base = 0; base < N_NODE; base += 1024) {
        int i = base + threadIdx.x;
        int v = (i < N_NODE) ? g_cnt[i] : 0;
        sdata[threadIdx.x] = v;
        __syncthreads();
        for (int off = 1; off < 1024; off <<= 1) {
            int t = (threadIdx.x >= off) ? sdata[threadIdx.x - off] : 0;
            __syncthreads();
            sdata[threadIdx.x] += t;
            __syncthreads();
        }
        int excl = sdata[threadIdx.x] - v;
        int r = s_running;
        if (i < N_NODE) { g_row_ptr[i] = r + excl; g_row_fill[i] = r + excl; }
        __syncthreads();
        if (threadIdx.x == 0) s_running = r + sdata[1023];
        __syncthreads();
    }
    if (threadIdx.x == 0) g_row_ptr[N_NODE] = s_running;
}

__global__ void k_scatter(const float* __restrict__ vals,
                          const int* __restrict__ rows,
                          const int* __restrict__ cols) {
    int i = blockIdx.x * blockDim.x + threadIdx.x;
    if (i < NNZ) {
        int pos = atomicAdd(&g_row_fill[rows[i]], 1);
        g_csr_val[pos] = vals[i];
        g_csr_col[pos] = cols[i];
    }
}

// ---------------- SpMM: one warp per row, float4 lanes, no float atomics -----
__global__ void k_spmm(const float* __restrict__ emb, int mode) {
    const float* __restrict__ x = (mode == 0) ? emb : g_buf1;
    float* __restrict__ y       = (mode == 0) ? g_buf1 : g_buf2;

    int warp = (blockIdx.x * blockDim.x + threadIdx.x) >> 5;
    int lane = threadIdx.x & 31;
    if (warp >= N_NODE) return;

    int s = g_row_ptr[warp];
    int e = g_row_ptr[warp + 1];
    bool act = lane < (EMB / 4);   // 28 active lanes
    float4 acc = make_float4(0.f, 0.f, 0.f, 0.f);

    for (int k = s; k < e; k++) {
        float v = g_csr_val[k];      // broadcast
        int   c = g_csr_col[k];      // broadcast
        if (act) {
            const float4 xv = *reinterpret_cast<const float4*>(
                x + (size_t)c * EMB + lane * 4);
            acc.x += v * xv.x;
            acc.y += v * xv.y;
            acc.z += v * xv.z;
            acc.w += v * xv.w;
        }
    }
    if (act)
        *reinterpret_cast<float4*>(y + (size_t)warp * EMB + lane * 4) = acc;
}

// ---------------- session pooling: sess = sum_l item_emb[items]/len ----------
__global__ void k_pool(const float* __restrict__ emb,
                       const int* __restrict__ items,
                       const float* __restrict__ slen) {
    int b = blockIdx.x;
    int c = threadIdx.x;          // 112 threads
    float acc = 0.f;
    #pragma unroll 5
    for (int l = 0; l < SEQL; l++) {
        int it = items[b * SEQL + l];
        if (it > 0) {
            size_t o = (size_t)(it - 1) * EMB + c;
            acc += emb[o] + g_buf1[o] + g_buf2[o];   // (emb+cur1+cur2)
        }
    }
    float v = acc * (1.0f / 3.0f) / slen[b];
    g_sess[b * EMB + c]  = v;
    g_accum[b * EMB + c] = v;
}

// ---------------- DA = D @ A (512x512x512 tiled) ------------------------------
__global__ void k_mm512(const float* __restrict__ D, const float* __restrict__ A) {
    __shared__ float sD[32][33];
    __shared__ float sA[32][33];
    int tx = threadIdx.x, ty = threadIdx.y;
    int row = blockIdx.y * 32 + ty;
    int col = blockIdx.x * 32 + tx;
    float acc = 0.f;
    for (int k0 = 0; k0 < 512; k0 += 32) {
        sD[ty][tx] = D[row * 512 + k0 + tx];
        sA[ty][tx] = A[(k0 + ty) * 512 + col];
        __syncthreads();
        #pragma unroll
        for (int k = 0; k < 32; k++) acc += sD[ty][k] * sA[k][tx];
        __syncthreads();
    }
    g_DA[row * 512 + col] = acc;
}

// ---------------- tmp = sess @ W^T  (per-session block) ----------------------
__global__ void k_linear(const float* __restrict__ w) {
    __shared__ float s[EMB];
    int b = blockIdx.x;
    int o = threadIdx.x;          // 112 threads
    s[o] = g_sess[b * EMB + o];
    __syncthreads();
    float acc = 0.f;
    #pragma unroll 8
    for (int k = 0; k < EMB; k++) acc += s[k] * w[o * EMB + k];
    g_tmp[b * EMB + o] = acc;
}

// ---------------- sess = l2norm(DA @ tmp); accum += sess ---------------------
__global__ void k_danorm() {
    int b = blockIdx.x;
    int c = threadIdx.x;          // 128 threads, 112 active
    float acc = 0.f;
    if (c < EMB) {
        const float* __restrict__ da = &g_DA[b * 512];
        #pragma unroll 8
        for (int j = 0; j < 512; j++) acc += da[j] * g_tmp[j * EMB + c];
    }
    __shared__ float red[128];
    red[threadIdx.x] = (c < EMB) ? acc * acc : 0.f;
    __syncthreads();
    for (int off = 64; off > 0; off >>= 1) {
        if (threadIdx.x < off) red[threadIdx.x] += red[threadIdx.x + off];
        __syncthreads();
    }
    float inv = 1.0f / fmaxf(sqrtf(red[0]), 1e-12f);
    if (c < EMB) {
        float v = acc * inv;
        g_sess[b * EMB + c]   = v;
        g_accum[b * EMB + c] += v;
    }
}

__global__ void k_final(float* __restrict__ out) {
    int i = blockIdx.x * blockDim.x + threadIdx.x;
    if (i < BATCH * EMB) out[i] = g_accum[i] * (1.0f / 3.0f);
}

// ---------------- launch ------------------------------------------------------
extern "C" void kernel_launch(void* const* d_in, const int* in_sizes, int n_in,
                              void* d_out, int out_size) {
    const float* emb   = (const float*)d_in[0];
    const float* vals  = (const float*)d_in[1];
    const int*   rows  = (const int*)d_in[2];
    const int*   cols  = (const int*)d_in[3];
    const float* D     = (const float*)d_in[4];
    const float* A     = (const float*)d_in[5];
    const int*   items = (const int*)d_in[6];
    const float* slen  = (const float*)d_in[7];
    const float* wsess = (const float*)d_in[8];
    float* out = (float*)d_out;

    (void)in_sizes; (void)n_in; (void)out_size;

    // CSR build
    k_zero_cnt<<<(N_NODE + 256) / 256, 256>>>();
    k_count<<<(NNZ + 255) / 256, 256>>>(rows);
    k_scan<<<1, 1024>>>();
    k_scatter<<<(NNZ + 255) / 256, 256>>>(vals, rows, cols);

    // hyperconv: cur1 = A@emb ; cur2 = A@cur1
    const int spmm_blocks = (N_NODE * 32 + 255) / 256;
    k_spmm<<<spmm_blocks, 256>>>(emb, 0);
    k_spmm<<<spmm_blocks, 256>>>(emb, 1);

    // sessconv
    k_pool<<<BATCH, EMB>>>(emb, items, slen);
    k_mm512<<<dim3(16, 16), dim3(32, 32)>>>(D, A);

    k_linear<<<BATCH, EMB>>>(wsess + 0 * EMB * EMB);
    k_danorm<<<BATCH, 128>>>();
    k_linear<<<BATCH, EMB>>>(wsess + 1 * EMB * EMB);
    k_danorm<<<BATCH, 128>>>();

    k_final<<<(BATCH * EMB + 255) / 256, 256>>>(out);
}

// round 2
// speedup vs baseline: 1.2363x; 1.2363x over previous
#include <cuda_runtime.h>

#define N_NODE 100000
#define EMB    112
#define NNZ    1000000
#define BATCH  512
#define SEQL   50
#define MAXNEED (BATCH * SEQL)

// ---------------- scratch (device globals; no allocations allowed) ----------
__device__ int   g_cnt[N_NODE + 1];
__device__ int   g_row_ptr[N_NODE + 1];
__device__ int   g_row_fill[N_NODE];
__device__ int   g_flag[N_NODE];
__device__ int   g_need[MAXNEED];
__device__ int   g_nneed;
__device__ float g_csr_val[NNZ];
__device__ int   g_csr_col[NNZ];
__device__ float g_buf1[(size_t)N_NODE * EMB];
__device__ float g_buf2[(size_t)N_NODE * EMB];
__device__ float g_sess[BATCH * EMB];
__device__ float g_tmp[BATCH * EMB];
__device__ float g_accum[BATCH * EMB];
__device__ float g_DA[BATCH * BATCH];

// ---------------- init: zero counters + flags --------------------------------
__global__ void k_zero() {
    int i = blockIdx.x * blockDim.x + threadIdx.x;
    if (i <= N_NODE) g_cnt[i] = 0;
    if (i < N_NODE)  g_flag[i] = 0;
    if (i == 0)      g_nneed = 0;
}

// mark rows whose layer-2 output is actually consumed by the session pool
__global__ void k_mark(const int* __restrict__ items) {
    int i = blockIdx.x * blockDim.x + threadIdx.x;
    if (i < BATCH * SEQL) {
        int it = items[i];
        if (it > 0) g_flag[it - 1] = 1;
    }
}

__global__ void k_compact() {
    int i = blockIdx.x * blockDim.x + threadIdx.x;
    if (i < N_NODE && g_flag[i]) {
        int p = atomicAdd(&g_nneed, 1);
        g_need[p] = i;
    }
}

__global__ void k_count(const int* __restrict__ rows) {
    int i = blockIdx.x * blockDim.x + threadIdx.x;
    if (i < NNZ) atomicAdd(&g_cnt[rows[i]], 1);
}

// single-block exclusive scan, warp-shuffle based, 4 elements / thread
__global__ void k_scan() {
    __shared__ int warpsum[32];
    __shared__ int s_running;
    const int tid  = threadIdx.x;
    const int lane = tid & 31;
    const int wid  = tid >> 5;
    if (tid == 0) s_running = 0;
    __syncthreads();

    const int TILE = 4096;                       // 1024 threads * 4
    for (int base = 0; base < N_NODE; base += TILE) {
        int i0 = base + tid * 4;
        int v0 = (i0 + 0 < N_NODE) ? g_cnt[i0 + 0] : 0;
        int v1 = (i0 + 1 < N_NODE) ? g_cnt[i0 + 1] : 0;
        int v2 = (i0 + 2 < N_NODE) ? g_cnt[i0 + 2] : 0;
        int v3 = (i0 + 3 < N_NODE) ? g_cnt[i0 + 3] : 0;
        int tsum = v0 + v1 + v2 + v3;

        // warp inclusive scan of per-thread sums
        int inc = tsum;
        #pragma unroll
        for (int off = 1; off < 32; off <<= 1) {
            int t = __shfl_up_sync(0xffffffffu, inc, off);
            if (lane >= off) inc += t;
        }
        if (lane == 31) warpsum[wid] = inc;
        __syncthreads();
        if (wid == 0) {                          // scan the 32 warp sums
            int ws = warpsum[lane];
            #pragma unroll
            for (int off = 1; off < 32; off <<= 1) {
                int t = __shfl_up_sync(0xffffffffu, ws, off);
                if (lane >= off) ws += t;
            }
            warpsum[lane] = ws;                  // inclusive
        }
        __syncthreads();

        int excl = inc - tsum + (wid > 0 ? warpsum[wid - 1] : 0) + s_running;
        int run = excl;
        if (i0 + 0 < N_NODE) { g_row_ptr[i0 + 0] = run; g_row_fill[i0 + 0] = run; run += v0; }
        if (i0 + 1 < N_NODE) { g_row_ptr[i0 + 1] = run; g_row_fill[i0 + 1] = run; run += v1; }
        if (i0 + 2 < N_NODE) { g_row_ptr[i0 + 2] = run; g_row_fill[i0 + 2] = run; run += v2; }
        if (i0 + 3 < N_NODE) { g_row_ptr[i0 + 3] = run; g_row_fill[i0 + 3] = run; run += v3; }
        __syncthreads();                          // everyone done reading s_running / warpsum
        if (tid == 0) s_running += warpsum[31];
        __syncthreads();
    }
    if (tid == 0) g_row_ptr[N_NODE] = s_running;
}

__global__ void k_scatter(const float* __restrict__ vals,
                          const int* __restrict__ rows,
                          const int* __restrict__ cols) {
    int i = blockIdx.x * blockDim.x + threadIdx.x;
    if (i < NNZ) {
        int pos = atomicAdd(&g_row_fill[rows[i]], 1);
        g_csr_val[pos] = vals[i];
        g_csr_col[pos] = cols[i];
    }
}

// ---------------- SpMM core: warp computes one row, 2 edges in flight --------
__device__ __forceinline__ void spmm_row(int row, const float* __restrict__ x,
                                         float* __restrict__ y, int lane) {
    int s = g_row_ptr[row];
    int e = g_row_ptr[row + 1];
    bool act = lane < (EMB / 4);                  // 28 active lanes
    float4 acc = make_float4(0.f, 0.f, 0.f, 0.f);

    int k = s;
    for (; k + 1 < e; k += 2) {                   // 2-deep software pipeline
        float v0 = g_csr_val[k];
        int   c0 = g_csr_col[k];
        float v1 = g_csr_val[k + 1];
        int   c1 = g_csr_col[k + 1];
        if (act) {
            float4 a = *reinterpret_cast<const float4*>(x + (size_t)c0 * EMB + lane * 4);
            float4 b = *reinterpret_cast<const float4*>(x + (size_t)c1 * EMB + lane * 4);
            acc.x += v0 * a.x + v1 * b.x;
            acc.y += v0 * a.y + v1 * b.y;
            acc.z += v0 * a.z + v1 * b.z;
            acc.w += v0 * a.w + v1 * b.w;
        }
    }
    if (k < e) {
        float v = g_csr_val[k];
        int   c = g_csr_col[k];
        if (act) {
            float4 a = *reinterpret_cast<const float4*>(x + (size_t)c * EMB + lane * 4);
            acc.x += v * a.x; acc.y += v * a.y; acc.z += v * a.z; acc.w += v * a.w;
        }
    }
    if (act)
        *reinterpret_cast<float4*>(y + (size_t)row * EMB + lane * 4) = acc;
}

// pass 1: all rows (output feeds pass-2 gathers at arbitrary columns)
__global__ void k_spmm1(const float* __restrict__ emb) {
    int warp = (blockIdx.x * blockDim.x + threadIdx.x) >> 5;
    int lane = threadIdx.x & 31;
    if (warp >= N_NODE) return;
    spmm_row(warp, emb, g_buf1, lane);
}

// pass 2: only session-referenced rows
__global__ void k_spmm2() {
    int widx = (blockIdx.x * blockDim.x + threadIdx.x) >> 5;
    int lane = threadIdx.x & 31;
    if (widx >= g_nneed) return;
    spmm_row(g_need[widx], g_buf1, g_buf2, lane);
}

// ---------------- session pooling ---------------------------------------------
__global__ void k_pool(const float* __restrict__ emb,
                       const int* __restrict__ items,
                       const float* __restrict__ slen) {
    int b = blockIdx.x;
    int c = threadIdx.x;                          // 112 threads
    float acc = 0.f;
    #pragma unroll 5
    for (int l = 0; l < SEQL; l++) {
        int it = items[b * SEQL + l];
        if (it > 0) {
            size_t o = (size_t)(it - 1) * EMB + c;
            acc += emb[o] + g_buf1[o] + g_buf2[o];
        }
    }
    float v = acc * (1.0f / 3.0f) / slen[b];
    g_sess[b * EMB + c]  = v;
    g_accum[b * EMB + c] = v;
}

// ---------------- DA = D @ A ---------------------------------------------------
__global__ void k_mm512(const float* __restrict__ D, const float* __restrict__ A) {
    __shared__ float sD[32][33];
    __shared__ float sA[32][33];
    int tx = threadIdx.x, ty = threadIdx.y;
    int row = blockIdx.y * 32 + ty;
    int col = blockIdx.x * 32 + tx;
    float acc = 0.f;
    for (int k0 = 0; k0 < 512; k0 += 32) {
        sD[ty][tx] = D[row * 512 + k0 + tx];
        sA[ty][tx] = A[(k0 + ty) * 512 + col];
        __syncthreads();
        #pragma unroll
        for (int k = 0; k < 32; k++) acc += sD[ty][k] * sA[k][tx];
        __syncthreads();
    }
    g_DA[row * 512 + col] = acc;
}

// ---------------- tmp = sess @ W^T ---------------------------------------------
__global__ void k_linear(const float* __restrict__ w) {
    __shared__ float s[EMB];
    int b = blockIdx.x;
    int o = threadIdx.x;                          // 112 threads
    s[o] = g_sess[b * EMB + o];
    __syncthreads();
    float acc = 0.f;
    #pragma unroll 8
    for (int k = 0; k < EMB; k++) acc += s[k] * w[o * EMB + k];
    g_tmp[b * EMB + o] = acc;
}

// ---------------- sess = l2norm(DA @ tmp); accum += ; optional final write -----
__global__ void k_danorm(int last, float* __restrict__ out) {
    int b = blockIdx.x;
    int c = threadIdx.x;                          // 128 threads, 112 active
    float acc = 0.f;
    if (c < EMB) {
        const float* __restrict__ da = &g_DA[b * 512];
        #pragma unroll 8
        for (int j = 0; j < 512; j++) acc += da[j] * g_tmp[j * EMB + c];
    }
    __shared__ float red[128];
    red[threadIdx.x] = (c < EMB) ? acc * acc : 0.f;
    __syncthreads();
    for (int off = 64; off > 0; off >>= 1) {
        if (threadIdx.x < off) red[threadIdx.x] += red[threadIdx.x + off];
        __syncthreads();
    }
    float inv = 1.0f / fmaxf(sqrtf(red[0]), 1e-12f);
    if (c < EMB) {
        float v = acc * inv;
        if (last) {
            out[b * EMB + c] = (g_accum[b * EMB + c] + v) * (1.0f / 3.0f);
        } else {
            g_sess[b * EMB + c]   = v;
            g_accum[b * EMB + c] += v;
        }
    }
}

// ---------------- launch --------------------------------------------------------
extern "C" void kernel_launch(void* const* d_in, const int* in_sizes, int n_in,
                              void* d_out, int out_size) {
    const float* emb   = (const float*)d_in[0];
    const float* vals  = (const float*)d_in[1];
    const int*   rows  = (const int*)d_in[2];
    const int*   cols  = (const int*)d_in[3];
    const float* D     = (const float*)d_in[4];
    const float* A     = (const float*)d_in[5];
    const int*   items = (const int*)d_in[6];
    const float* slen  = (const float*)d_in[7];
    const float* wsess = (const float*)d_in[8];
    float* out = (float*)d_out;

    (void)in_sizes; (void)n_in; (void)out_size;

    // CSR build + needed-row set
    k_zero<<<(N_NODE + 256) / 256, 256>>>();
    k_mark<<<(BATCH * SEQL + 255) / 256, 256>>>(items);
    k_count<<<(NNZ + 255) / 256, 256>>>(rows);
    k_scan<<<1, 1024>>>();
    k_scatter<<<(NNZ + 255) / 256, 256>>>(vals, rows, cols);
    k_compact<<<(N_NODE + 255) / 256, 256>>>();

    // hyperconv
    const int spmm1_blocks = (N_NODE * 32 + 255) / 256;
    k_spmm1<<<spmm1_blocks, 256>>>(emb);
    const int spmm2_blocks = (MAXNEED * 32 + 255) / 256;   // worst-case grid, early exit
    k_spmm2<<<spmm2_blocks, 256>>>();

    // sessconv
    k_pool<<<BATCH, EMB>>>(emb, items, slen);
    k_mm512<<<dim3(16, 16), dim3(32, 32)>>>(D, A);

    k_linear<<<BATCH, EMB>>>(wsess + 0 * EMB * EMB);
    k_danorm<<<BATCH, 128>>>(0, out);
    k_linear<<<BATCH, EMB>>>(wsess + 1 * EMB * EMB);
    k_danorm<<<BATCH, 128>>>(1, out);
}

// round 3
// speedup vs baseline: 1.6060x; 1.2990x over previous
#include <cuda_runtime.h>

#define N_NODE 100000
#define EMB    112
#define NNZ    1000000
#define BATCH  512
#define SEQL   50
#define MAXNEED (BATCH * SEQL)

#define SCAN_BLK 512
#define SCAN_NB  ((N_NODE + SCAN_BLK - 1) / SCAN_BLK)   // 196

// ---------------- scratch (device globals; no allocations allowed) ----------
__device__ int   g_cnt[N_NODE];
__device__ int   g_row_ptr[N_NODE + 1];
__device__ int   g_row_fill[N_NODE];
__device__ int   g_blocksum[SCAN_NB];
__device__ int   g_flag[N_NODE];
__device__ int   g_need[MAXNEED];
__device__ int   g_nneed;
__device__ float g_csr_val[NNZ];
__device__ int   g_csr_col[NNZ];
__device__ float g_buf1[(size_t)N_NODE * EMB];
__device__ float g_buf2[(size_t)N_NODE * EMB];
__device__ float g_sess[BATCH * EMB];
__device__ float g_tmp[BATCH * EMB];
__device__ float g_accum[BATCH * EMB];
__device__ float g_DA[BATCH * BATCH];

// ---------------- init: zero counters + flags --------------------------------
__global__ void k_zero() {
    int i = blockIdx.x * blockDim.x + threadIdx.x;
    if (i < N_NODE) { g_cnt[i] = 0; g_flag[i] = 0; }
    if (i == 0)     g_nneed = 0;
}

__global__ void k_mark(const int* __restrict__ items) {
    int i = blockIdx.x * blockDim.x + threadIdx.x;
    if (i < BATCH * SEQL) {
        int it = items[i];
        if (it > 0) g_flag[it - 1] = 1;
    }
}

__global__ void k_compact() {
    int i = blockIdx.x * blockDim.x + threadIdx.x;
    if (i < N_NODE && g_flag[i]) {
        int p = atomicAdd(&g_nneed, 1);
        g_need[p] = i;
    }
}

__global__ void k_count(const int* __restrict__ rows) {
    int i = blockIdx.x * blockDim.x + threadIdx.x;
    if (i < NNZ) atomicAdd(&g_cnt[rows[i]], 1);
}

// ---------------- 3-phase grid-wide exclusive scan ----------------------------
// phase 1: block-local exclusive scan; writes partial row_ptr + block sums
__global__ void k_scan1() {
    __shared__ int ws[SCAN_BLK / 32];             // 16 warp sums
    const int tid  = threadIdx.x;
    const int lane = tid & 31;
    const int wid  = tid >> 5;
    const int i    = blockIdx.x * SCAN_BLK + tid;

    int v = (i < N_NODE) ? g_cnt[i] : 0;
    int inc = v;
    #pragma unroll
    for (int off = 1; off < 32; off <<= 1) {
        int t = __shfl_up_sync(0xffffffffu, inc, off);
        if (lane >= off) inc += t;
    }
    if (lane == 31) ws[wid] = inc;
    __syncthreads();
    if (wid == 0) {
        int s = (lane < SCAN_BLK / 32) ? ws[lane] : 0;
        #pragma unroll
        for (int off = 1; off < SCAN_BLK / 32; off <<= 1) {
            int t = __shfl_up_sync(0xffffffffu, s, off);
            if (lane >= off) s += t;
        }
        if (lane < SCAN_BLK / 32) ws[lane] = s;   // inclusive warp sums
    }
    __syncthreads();

    int excl = inc - v + (wid > 0 ? ws[wid - 1] : 0);
    if (i < N_NODE) g_row_ptr[i] = excl;          // partial (block-local)
    if (tid == SCAN_BLK - 1) g_blocksum[blockIdx.x] = excl + v;
}

// phase 2: single small block scans the 196 block sums (exclusive, in place)
__global__ void k_scan2() {
    __shared__ int ws[8];
    const int tid  = threadIdx.x;                 // 256 threads
    const int lane = tid & 31;
    const int wid  = tid >> 5;

    int v = (tid < SCAN_NB) ? g_blocksum[tid] : 0;
    int inc = v;
    #pragma unroll
    for (int off = 1; off < 32; off <<= 1) {
        int t = __shfl_up_sync(0xffffffffu, inc, off);
        if (lane >= off) inc += t;
    }
    if (lane == 31) ws[wid] = inc;
    __syncthreads();
    if (wid == 0) {
        int s = (lane < 8) ? ws[lane] : 0;
        #pragma unroll
        for (int off = 1; off < 8; off <<= 1) {
            int t = __shfl_up_sync(0xffffffffu, s, off);
            if (lane >= off) s += t;
        }
        if (lane < 8) ws[lane] = s;
    }
    __syncthreads();

    int excl = inc - v + (wid > 0 ? ws[wid - 1] : 0);
    if (tid < SCAN_NB) g_blocksum[tid] = excl;
    if (tid == SCAN_NB - 1) g_row_ptr[N_NODE] = excl + v;   // total = NNZ
}

// phase 3: propagate block offsets; finalize row_ptr and row_fill
__global__ void k_scan3() {
    int i = blockIdx.x * blockDim.x + threadIdx.x;
    if (i < N_NODE) {
        int p = g_row_ptr[i] + g_blocksum[i / SCAN_BLK];
        g_row_ptr[i]  = p;
        g_row_fill[i] = p;
    }
}

__global__ void k_scatter(const float* __restrict__ vals,
                          const int* __restrict__ rows,
                          const int* __restrict__ cols) {
    int i = blockIdx.x * blockDim.x + threadIdx.x;
    if (i < NNZ) {
        int pos = atomicAdd(&g_row_fill[rows[i]], 1);
        g_csr_val[pos] = vals[i];
        g_csr_col[pos] = cols[i];
    }
}

// ---------------- SpMM core: warp per row, 4 edges in flight ------------------
__device__ __forceinline__ void spmm_row(int row, const float* __restrict__ x,
                                         float* __restrict__ y, int lane) {
    int s = g_row_ptr[row];
    int e = g_row_ptr[row + 1];
    bool act = lane < (EMB / 4);                  // 28 active lanes
    float4 acc = make_float4(0.f, 0.f, 0.f, 0.f);

    int k = s;
    for (; k + 3 < e; k += 4) {                   // 4-deep software pipeline
        float v0 = g_csr_val[k];     int c0 = g_csr_col[k];
        float v1 = g_csr_val[k + 1]; int c1 = g_csr_col[k + 1];
        float v2 = g_csr_val[k + 2]; int c2 = g_csr_col[k + 2];
        float v3 = g_csr_val[k + 3]; int c3 = g_csr_col[k + 3];
        if (act) {
            float4 a = *reinterpret_cast<const float4*>(x + (size_t)c0 * EMB + lane * 4);
            float4 b = *reinterpret_cast<const float4*>(x + (size_t)c1 * EMB + lane * 4);
            float4 c = *reinterpret_cast<const float4*>(x + (size_t)c2 * EMB + lane * 4);
            float4 d = *reinterpret_cast<const float4*>(x + (size_t)c3 * EMB + lane * 4);
            acc.x += v0 * a.x + v1 * b.x + v2 * c.x + v3 * d.x;
            acc.y += v0 * a.y + v1 * b.y + v2 * c.y + v3 * d.y;
            acc.z += v0 * a.z + v1 * b.z + v2 * c.z + v3 * d.z;
            acc.w += v0 * a.w + v1 * b.w + v2 * c.w + v3 * d.w;
        }
    }
    for (; k < e; k++) {
        float v = g_csr_val[k];
        int   c = g_csr_col[k];
        if (act) {
            float4 a = *reinterpret_cast<const float4*>(x + (size_t)c * EMB + lane * 4);
            acc.x += v * a.x; acc.y += v * a.y; acc.z += v * a.z; acc.w += v * a.w;
        }
    }
    if (act)
        *reinterpret_cast<float4*>(y + (size_t)row * EMB + lane * 4) = acc;
}

__global__ void k_spmm1(const float* __restrict__ emb) {
    int warp = (blockIdx.x * blockDim.x + threadIdx.x) >> 5;
    int lane = threadIdx.x & 31;
    if (warp >= N_NODE) return;
    spmm_row(warp, emb, g_buf1, lane);
}

__global__ void k_spmm2() {
    int widx = (blockIdx.x * blockDim.x + threadIdx.x) >> 5;
    int lane = threadIdx.x & 31;
    if (widx >= g_nneed) return;
    spmm_row(g_need[widx], g_buf1, g_buf2, lane);
}

// ---------------- session pooling ---------------------------------------------
__global__ void k_pool(const float* __restrict__ emb,
                       const int* __restrict__ items,
                       const float* __restrict__ slen) {
    int b = blockIdx.x;
    int c = threadIdx.x;                          // 112 threads
    float acc = 0.f;
    #pragma unroll 5
    for (int l = 0; l < SEQL; l++) {
        int it = items[b * SEQL + l];
        if (it > 0) {
            size_t o = (size_t)(it - 1) * EMB + c;
            acc += emb[o] + g_buf1[o] + g_buf2[o];
        }
    }
    float v = acc * (1.0f / 3.0f) / slen[b];
    g_sess[b * EMB + c]  = v;
    g_accum[b * EMB + c] = v;
}

// ---------------- DA = D @ A ---------------------------------------------------
__global__ void k_mm512(const float* __restrict__ D, const float* __restrict__ A) {
    __shared__ float sD[32][33];
    __shared__ float sA[32][33];
    int tx = threadIdx.x, ty = threadIdx.y;
    int row = blockIdx.y * 32 + ty;
    int col = blockIdx.x * 32 + tx;
    float acc = 0.f;
    for (int k0 = 0; k0 < 512; k0 += 32) {
        sD[ty][tx] = D[row * 512 + k0 + tx];
        sA[ty][tx] = A[(k0 + ty) * 512 + col];
        __syncthreads();
        #pragma unroll
        for (int k = 0; k < 32; k++) acc += sD[ty][k] * sA[k][tx];
        __syncthreads();
    }
    g_DA[row * 512 + col] = acc;
}

// ---------------- tmp = sess @ W^T ---------------------------------------------
__global__ void k_linear(const float* __restrict__ w) {
    __shared__ float s[EMB];
    int b = blockIdx.x;
    int o = threadIdx.x;                          // 112 threads
    s[o] = g_sess[b * EMB + o];
    __syncthreads();
    float acc = 0.f;
    #pragma unroll 8
    for (int k = 0; k < EMB; k++) acc += s[k] * w[o * EMB + k];
    g_tmp[b * EMB + o] = acc;
}

// ---------------- sess = l2norm(DA @ tmp); accum += ; optional final write -----
__global__ void k_danorm(int last, float* __restrict__ out) {
    int b = blockIdx.x;
    int c = threadIdx.x;                          // 128 threads, 112 active
    float acc = 0.f;
    if (c < EMB) {
        const float* __restrict__ da = &g_DA[b * 512];
        #pragma unroll 8
        for (int j = 0; j < 512; j++) acc += da[j] * g_tmp[j * EMB + c];
    }
    __shared__ float red[128];
    red[threadIdx.x] = (c < EMB) ? acc * acc : 0.f;
    __syncthreads();
    for (int off = 64; off > 0; off >>= 1) {
        if (threadIdx.x < off) red[threadIdx.x] += red[threadIdx.x + off];
        __syncthreads();
    }
    float inv = 1.0f / fmaxf(sqrtf(red[0]), 1e-12f);
    if (c < EMB) {
        float v = acc * inv;
        if (last) {
            out[b * EMB + c] = (g_accum[b * EMB + c] + v) * (1.0f / 3.0f);
        } else {
            g_sess[b * EMB + c]   = v;
            g_accum[b * EMB + c] += v;
        }
    }
}

// ---------------- launch --------------------------------------------------------
extern "C" void kernel_launch(void* const* d_in, const int* in_sizes, int n_in,
                              void* d_out, int out_size) {
    const float* emb   = (const float*)d_in[0];
    const float* vals  = (const float*)d_in[1];
    const int*   rows  = (const int*)d_in[2];
    const int*   cols  = (const int*)d_in[3];
    const float* D     = (const float*)d_in[4];
    const float* A     = (const float*)d_in[5];
    const int*   items = (const int*)d_in[6];
    const float* slen  = (const float*)d_in[7];
    const float* wsess = (const float*)d_in[8];
    float* out = (float*)d_out;

    (void)in_sizes; (void)n_in; (void)out_size;

    // CSR build + needed-row set
    k_zero<<<(N_NODE + 255) / 256, 256>>>();
    k_mark<<<(BATCH * SEQL + 255) / 256, 256>>>(items);
    k_count<<<(NNZ + 255) / 256, 256>>>(rows);
    k_scan1<<<SCAN_NB, SCAN_BLK>>>();
    k_scan2<<<1, 256>>>();
    k_scan3<<<(N_NODE + 255) / 256, 256>>>();
    k_scatter<<<(NNZ + 255) / 256, 256>>>(vals, rows, cols);
    k_compact<<<(N_NODE + 255) / 256, 256>>>();

    // hyperconv
    const int spmm1_blocks = (N_NODE * 32 + 255) / 256;
    k_spmm1<<<spmm1_blocks, 256>>>(emb);
    const int spmm2_blocks = (MAXNEED * 32 + 255) / 256;   // worst-case grid, early exit
    k_spmm2<<<spmm2_blocks, 256>>>();

    // sessconv
    k_pool<<<BATCH, EMB>>>(emb, items, slen);
    k_mm512<<<dim3(16, 16), dim3(32, 32)>>>(D, A);

    k_linear<<<BATCH, EMB>>>(wsess + 0 * EMB * EMB);
    k_danorm<<<BATCH, 128>>>(0, out);
    k_linear<<<BATCH, EMB>>>(wsess + 1 * EMB * EMB);
    k_danorm<<<BATCH, 128>>>(1, out);
}